// round 15
// baseline (speedup 1.0000x reference)
#include <cuda_runtime.h>
#include <cuda_bf16.h>
#include <cstdint>

// Problem dims (fixed by reference)
#define BQ    4
#define SQ    2048
#define DM    1024
#define HID   4096
#define NH    16
#define DH    64
#define DIL   2
#define LQ    (SQ / DIL)          // 1024
#define MTOK  (BQ * SQ)           // 8192 tokens
#define QKS   3072                // concatenated QKV width

// ---------------- scratch (static device globals) ---------------------------
__device__ float g_res1[(size_t)MTOK * DM];
__device__ float g_fin [(size_t)MTOK * DM];
__device__ float g_res2[(size_t)MTOK * DM];
__device__ float g_bqkv[QKS];

// bf16 hi/lo buffers
__device__ __nv_bfloat16 g_xh[(size_t)MTOK * DM];
__device__ __nv_bfloat16 g_xl[(size_t)MTOK * DM];
__device__ __nv_bfloat16 g_qkvh[(size_t)MTOK * QKS];
__device__ __nv_bfloat16 g_qkvl[(size_t)MTOK * QKS];
__device__ __nv_bfloat16 g_ch[(size_t)MTOK * DM];
__device__ __nv_bfloat16 g_cl[(size_t)MTOK * DM];
__device__ __nv_bfloat16 g_fh[(size_t)MTOK * DM];
__device__ __nv_bfloat16 g_fl[(size_t)MTOK * DM];
__device__ __nv_bfloat16 g_hh[(size_t)MTOK * HID];
__device__ __nv_bfloat16 g_hl[(size_t)MTOK * HID];
__device__ __nv_bfloat16 g_wqkvh[(size_t)DM * QKS];
__device__ __nv_bfloat16 g_wqkvl[(size_t)DM * QKS];
__device__ __nv_bfloat16 g_woh[(size_t)DM * DM];
__device__ __nv_bfloat16 g_wol[(size_t)DM * DM];
__device__ __nv_bfloat16 g_w1h[(size_t)DM * HID];
__device__ __nv_bfloat16 g_w1l[(size_t)DM * HID];
__device__ __nv_bfloat16 g_w2h[(size_t)HID * DM];
__device__ __nv_bfloat16 g_w2l[(size_t)HID * DM];

// ---------------- helpers ----------------------------------------------------
__device__ __forceinline__ uint32_t s2u(const void* p) {
    uint32_t a;
    asm("{ .reg .u64 t; cvta.to.shared.u64 t, %1; cvt.u32.u64 %0, t; }" : "=r"(a) : "l"(p));
    return a;
}

__device__ __forceinline__ uint32_t packbf2(float a, float b) {
    __nv_bfloat162 t;
    t.x = __float2bfloat16(a);
    t.y = __float2bfloat16(b);
    return *(uint32_t*)&t;
}

__device__ __forceinline__ float hibf(float a) {
    return __bfloat162float(__float2bfloat16(a));
}

__device__ __forceinline__ void mma16816(float* d, const uint32_t* a, const uint32_t* b) {
    asm volatile(
        "mma.sync.aligned.m16n8k16.row.col.f32.bf16.bf16.f32 "
        "{%0,%1,%2,%3}, {%4,%5,%6,%7}, {%8,%9}, {%0,%1,%2,%3};"
        : "+f"(d[0]), "+f"(d[1]), "+f"(d[2]), "+f"(d[3])
        : "r"(a[0]), "r"(a[1]), "r"(a[2]), "r"(a[3]), "r"(b[0]), "r"(b[1]));
}

__device__ __forceinline__ void ldsm4(uint32_t* r, uint32_t addr) {
    asm volatile("ldmatrix.sync.aligned.m8n8.x4.shared.b16 {%0,%1,%2,%3}, [%4];"
                 : "=r"(r[0]), "=r"(r[1]), "=r"(r[2]), "=r"(r[3]) : "r"(addr));
}

__device__ __forceinline__ void ldsm4t(uint32_t* r, uint32_t addr) {
    asm volatile("ldmatrix.sync.aligned.m8n8.x4.trans.shared.b16 {%0,%1,%2,%3}, [%4];"
                 : "=r"(r[0]), "=r"(r[1]), "=r"(r[2]), "=r"(r[3]) : "r"(addr));
}

__device__ __forceinline__ void cpasync16(uint32_t dst, const void* src) {
    asm volatile("cp.async.cg.shared.global [%0], [%1], 16;" :: "r"(dst), "l"(src));
}
__device__ __forceinline__ void cpcommit() {
    asm volatile("cp.async.commit_group;" ::: "memory");
}
__device__ __forceinline__ void cpwait1() {
    asm volatile("cp.async.wait_group 1;" ::: "memory");
}
__device__ __forceinline__ void cpwait0() {
    asm volatile("cp.async.wait_group 0;" ::: "memory");
}

// ---------------- bf16x3 HMMA GEMM: 3-stage, single barrier per chunk --------
#define KT   32
#define PA   40
#define PB   136
#define ASZ  (128 * PA * 2)
#define BSZ  (KT * PB * 2)
#define STG  (2 * ASZ + 2 * BSZ)    // 37888 B per stage
#define DYN_SMEM (3 * STG)          // 113664 B; 2 CTAs/SM

template <int MODE, bool OUTBF16>
__global__ void __launch_bounds__(256, 2)
tgemm_kernel(const __nv_bfloat16* __restrict__ Ah, const __nv_bfloat16* __restrict__ Al,
             const __nv_bfloat16* __restrict__ Wh, const __nv_bfloat16* __restrict__ Wl,
             const float* __restrict__ bias, const float* __restrict__ Rres,
             float* __restrict__ C, __nv_bfloat16* __restrict__ Ch,
             __nv_bfloat16* __restrict__ Cl, int M, int N, int Kd)
{
    extern __shared__ __align__(16) char smem[];
    const uint32_t sb = s2u(smem);
    const int tid  = threadIdx.x;
    const int lane = tid & 31;
    const int wid  = tid >> 5;
    const int bm   = blockIdx.y;
    const int bn   = blockIdx.x;
    const int wm0  = (wid & 1) * 64;
    const int wn0  = (wid >> 1) * 32;

    const int ar  = tid >> 1;
    const int ak0 = (tid & 1) * 16;
    const int bk  = tid >> 3;
    const int bn0 = (tid & 7) * 16;

    const size_t aoff = (size_t)(bm * 128 + ar) * Kd + ak0;
    const size_t boff = (size_t)bk * N + bn * 128 + bn0;

    float acc[4][4][4];
#pragma unroll
    for (int i = 0; i < 4; i++)
#pragma unroll
        for (int j = 0; j < 4; j++)
#pragma unroll
            for (int l = 0; l < 4; l++) acc[i][j][l] = 0.f;

    const int nk = Kd / KT;

    auto issue_loads = [&](int kb, int buf) {
        const uint32_t s = sb + buf * STG;
        const uint32_t dAh = s + (ar * PA + ak0) * 2;
        const uint32_t dAl = dAh + ASZ;
        const uint32_t dBh = s + 2 * ASZ + (bk * PB + bn0) * 2;
        const uint32_t dBl = dBh + BSZ;
        const __nv_bfloat16* pAh = Ah + aoff + (size_t)kb * KT;
        const __nv_bfloat16* pAl = Al + aoff + (size_t)kb * KT;
        const __nv_bfloat16* pBh = Wh + boff + (size_t)kb * KT * N;
        const __nv_bfloat16* pBl = Wl + boff + (size_t)kb * KT * N;
        cpasync16(dAh,      pAh);
        cpasync16(dAh + 16, pAh + 8);
        cpasync16(dAl,      pAl);
        cpasync16(dAl + 16, pAl + 8);
        cpasync16(dBh,      pBh);
        cpasync16(dBh + 16, pBh + 8);
        cpasync16(dBl,      pBl);
        cpasync16(dBl + 16, pBl + 8);
        cpcommit();
    };

    // one k16 step of the chunk in buffer `buf`
    auto compute_k16 = [&](int buf, int ks) {
        const uint32_t base = sb + buf * STG;
        const uint32_t aAh = base;
        const uint32_t aAl = base + ASZ;
        const uint32_t aBh = base + 2 * ASZ;
        const uint32_t aBl = base + 2 * ASZ + BSZ;
        const int lr = lane & 15;
        const int lc = (lane >> 4) * 8;
        uint32_t bh[2][4], bl[2][4];
#pragma unroll
        for (int g = 0; g < 2; g++) {
            uint32_t off = ((ks + lr) * PB + wn0 + g * 16 + lc) * 2;
            ldsm4t(bh[g], aBh + off);
            ldsm4t(bl[g], aBl + off);
        }
#pragma unroll
        for (int mp = 0; mp < 4; mp += 2) {
            uint32_t ah[2][4], al[2][4];
#pragma unroll
            for (int i = 0; i < 2; i++) {
                uint32_t off = ((wm0 + (mp + i) * 16 + lr) * PA + ks + lc) * 2;
                ldsm4(ah[i], aAh + off);
                ldsm4(al[i], aAl + off);
            }
#pragma unroll
            for (int i = 0; i < 2; i++)
#pragma unroll
                for (int nt = 0; nt < 4; nt++) {
                    const int g = nt >> 1, q = (nt & 1) * 2;
                    uint32_t bb[2] = { bh[g][q], bh[g][q + 1] };
                    mma16816(acc[mp + i][nt], ah[i], bb);
                }
#pragma unroll
            for (int i = 0; i < 2; i++)
#pragma unroll
                for (int nt = 0; nt < 4; nt++) {
                    const int g = nt >> 1, q = (nt & 1) * 2;
                    uint32_t bb[2] = { bl[g][q], bl[g][q + 1] };
                    mma16816(acc[mp + i][nt], ah[i], bb);
                }
#pragma unroll
            for (int i = 0; i < 2; i++)
#pragma unroll
                for (int nt = 0; nt < 4; nt++) {
                    const int g = nt >> 1, q = (nt & 1) * 2;
                    uint32_t bb[2] = { bh[g][q], bh[g][q + 1] };
                    mma16816(acc[mp + i][nt], al[i], bb);
                }
        }
    };

    // prologue: 2 chunks in flight
    issue_loads(0, 0);
    issue_loads(1, 1);
    for (int kb = 0; kb < nk; kb++) {
        if (kb < nk - 1) cpwait1(); else cpwait0();
        __syncthreads();
        const int buf = kb % 3;
        compute_k16(buf, 0);
        if (kb + 2 < nk) issue_loads(kb + 2, (kb + 2) % 3);
        compute_k16(buf, 16);
    }

    const int rbase = bm * 128 + wm0 + (lane >> 2);
    const int cbase = bn * 128 + wn0 + (lane & 3) * 2;
#pragma unroll
    for (int mt = 0; mt < 4; mt++) {
#pragma unroll
        for (int hf = 0; hf < 2; hf++) {
            const int row = rbase + mt * 16 + hf * 8;
#pragma unroll
            for (int nt = 0; nt < 4; nt++) {
                const int col = cbase + nt * 8;
                float v0 = acc[mt][nt][hf * 2 + 0] + bias[col];
                float v1 = acc[mt][nt][hf * 2 + 1] + bias[col + 1];
                if (MODE == 1) {
                    v0 += Rres[(size_t)row * N + col];
                    v1 += Rres[(size_t)row * N + col + 1];
                }
                if (MODE == 2) { v0 = fmaxf(v0, 0.f); v1 = fmaxf(v1, 0.f); }
                if (OUTBF16) {
                    *(uint32_t*)(Ch + (size_t)row * N + col) = packbf2(v0, v1);
                    *(uint32_t*)(Cl + (size_t)row * N + col) =
                        packbf2(v0 - hibf(v0), v1 - hibf(v1));
                } else {
                    float2 o; o.x = v0; o.y = v1;
                    *(float2*)(C + (size_t)row * N + col) = o;
                }
            }
        }
    }
}

// ---------------- splits ------------------------------------------------------
__device__ __forceinline__ void split_one2(const float* __restrict__ X, int si,
                                           __nv_bfloat16* __restrict__ H,
                                           __nv_bfloat16* __restrict__ L, int di)
{
    float4 v = ((const float4*)X)[si];
    ((uint32_t*)H)[di * 2 + 0] = packbf2(v.x, v.y);
    ((uint32_t*)H)[di * 2 + 1] = packbf2(v.z, v.w);
    ((uint32_t*)L)[di * 2 + 0] = packbf2(v.x - hibf(v.x), v.y - hibf(v.y));
    ((uint32_t*)L)[di * 2 + 1] = packbf2(v.z - hibf(v.z), v.w - hibf(v.w));
}

__global__ void __launch_bounds__(256)
split_kernel(const float* __restrict__ X, __nv_bfloat16* __restrict__ H,
             __nv_bfloat16* __restrict__ L, int n4)
{
    int i = blockIdx.x * blockDim.x + threadIdx.x;
    if (i < n4) split_one2(X, i, H, L, i);
}

#define DD4 (DM * DM / 4)
#define DH4 (DM * HID / 4)
// Wq/Wk/Wv -> concatenated [1024][3072] hi/lo; Wo, W1, W2 plain; qkv bias concat.
__global__ void __launch_bounds__(256)
splitw_kernel(const float* Wq, const float* Wk, const float* Wv, const float* Wo,
              const float* W1, const float* W2,
              const float* bq, const float* bk, const float* bv, float* bqkv,
              __nv_bfloat16* wqkvh, __nv_bfloat16* wqkvl,
              __nv_bfloat16* woh, __nv_bfloat16* wol,
              __nv_bfloat16* w1h, __nv_bfloat16* w1l,
              __nv_bfloat16* w2h, __nv_bfloat16* w2l)
{
    int i = blockIdx.x * blockDim.x + threadIdx.x;
    if (i < 3 * DD4) {
        int m = i / DD4;                  // 0=q 1=k 2=v
        int j = i - m * DD4;
        int k = j >> 8;
        int c = j & 255;
        const float* src = (m == 0) ? Wq : (m == 1) ? Wk : Wv;
        split_one2(src, j, wqkvh, wqkvl, k * (QKS / 4) + m * 256 + c);
    } else {
        int j = i - 3 * DD4;
        if (j < DD4)                 split_one2(Wo, j, woh, wol, j);
        else if (j < DD4 + DH4)      split_one2(W1, j - DD4, w1h, w1l, j - DD4);
        else if (j < DD4 + 2 * DH4)  split_one2(W2, j - DD4 - DH4, w2h, w2l, j - DD4 - DH4);
        else {
            int t = j - DD4 - 2 * DH4;   // 0..QKS-1
            if (t < DM)            bqkv[t] = bq[t];
            else if (t < 2 * DM)   bqkv[t] = bk[t - DM];
            else if (t < 3 * DM)   bqkv[t] = bv[t - 2 * DM];
        }
    }
}

// ---------------- HMMA flash attention (reads strided QKV buffer) ------------
// Q fragments reloaded from SMEM per kk; warp-uniform rescale skip.
#define FP    72
#define FPB   144
#define FQH   0
#define FQL   18432
#define FKV0  36864
#define FSSZ  36864
#define FKH   0
#define FKL   9216
#define FVH   18432
#define FVL   27648
#define FLASH_SMEM (36864 + 2 * FSSZ)
#define CSC   0.180336879f

__global__ void __launch_bounds__(256, 2)
flashmma_kernel(const __nv_bfloat16* __restrict__ qkvh, const __nv_bfloat16* __restrict__ qkvl,
                __nv_bfloat16* __restrict__ och, __nv_bfloat16* __restrict__ ocl)
{
    extern __shared__ __align__(16) char fsm[];
    const uint32_t sb = s2u(fsm);
    const int tid  = threadIdx.x;
    const int lane = tid & 31;
    const int w    = tid >> 5;
    const int gh   = blockIdx.x;
    const int qt   = blockIdx.y;
    const int g    = gh >> 4;
    const int h    = gh & 15;
    const int b    = g >> 1;
    const int di   = g & 1;
    const int m0   = w * 16;

    const __nv_bfloat16* qh = qkvh;
    const __nv_bfloat16* ql = qkvl;
    const __nv_bfloat16* kh = qkvh + DM;
    const __nv_bfloat16* kl = qkvl + DM;
    const __nv_bfloat16* vh = qkvh + 2 * DM;
    const __nv_bfloat16* vl = qkvl + 2 * DM;

    auto ldq = [&]() {
#pragma unroll
        for (int i = 0; i < 8; i++) {
            int c   = tid + i * 256;
            int hf  = c >> 10;
            int cc  = c & 1023;
            int row = cc >> 3;
            int o   = cc & 7;
            size_t tok = (size_t)(b * SQ + 2 * (qt * 128 + row) + di);
            const __nv_bfloat16* src = (hf ? ql : qh) + tok * QKS + h * DH + o * 8;
            cpasync16(sb + (hf ? FQL : FQH) + row * FPB + o * 16, src);
        }
    };
    auto ldkv = [&](int kt, int s) {
        const uint32_t base = sb + FKV0 + s * FSSZ;
#pragma unroll
        for (int i = 0; i < 8; i++) {
            int c   = tid + i * 256;
            int mat = c >> 9;
            int cc  = c & 511;
            int row = cc >> 3;
            int o   = cc & 7;
            size_t tok = (size_t)(b * SQ + 2 * (kt * 64 + row) + di);
            const __nv_bfloat16* srcp =
                (mat == 0) ? kh : (mat == 1) ? kl : (mat == 2) ? vh : vl;
            cpasync16(base + mat * 9216 + row * FPB + o * 16, srcp + tok * QKS + h * DH + o * 8);
        }
    };

    ldq();
    ldkv(0, 0);
    cpcommit();
    ldkv(1, 1);
    cpcommit();

    float oacc[8][4];
#pragma unroll
    for (int n = 0; n < 8; n++)
#pragma unroll
        for (int i = 0; i < 4; i++) oacc[n][i] = 0.f;
    float mA = -1e30f, mB = -1e30f, lA = 0.f, lB = 0.f;

    const int arow = (lane & 7) + ((lane >> 3) & 1) * 8;
    const int acol = (lane >> 4) * 16;

    for (int kt = 0; kt < LQ / 64; kt++) {
        if (kt == LQ / 64 - 1) cpwait0(); else cpwait1();
        __syncthreads();
        const uint32_t base = sb + FKV0 + (kt & 1) * FSSZ;

        float sacc[8][4];
#pragma unroll
        for (int n = 0; n < 8; n++)
#pragma unroll
            for (int i = 0; i < 4; i++) sacc[n][i] = 0.f;

#pragma unroll
        for (int kk = 0; kk < 4; kk++) {
            // reload Q fragments for this k-slice from SMEM (regs stay low)
            uint32_t qhf[4], qlf[4];
            {
                uint32_t qoff = (m0 + arow) * FPB + kk * 32 + acol;
                ldsm4(qhf, sb + FQH + qoff);
                ldsm4(qlf, sb + FQL + qoff);
            }
            uint32_t kbh[4][4], kbl[4][4];
#pragma unroll
            for (int j = 0; j < 4; j++) {
                int key = j * 16 + (lane & 7) + ((lane >> 4) << 3);
                uint32_t off = key * FPB + kk * 32 + ((lane >> 3) & 1) * 16;
                ldsm4(kbh[j], base + FKH + off);
                ldsm4(kbl[j], base + FKL + off);
            }
#pragma unroll
            for (int j = 0; j < 4; j++) {
                uint32_t b0[2] = { kbh[j][0], kbh[j][1] };
                uint32_t b1[2] = { kbh[j][2], kbh[j][3] };
                mma16816(sacc[2 * j],     qhf, b0);
                mma16816(sacc[2 * j + 1], qhf, b1);
            }
#pragma unroll
            for (int j = 0; j < 4; j++) {
                uint32_t b0[2] = { kbl[j][0], kbl[j][1] };
                uint32_t b1[2] = { kbl[j][2], kbl[j][3] };
                mma16816(sacc[2 * j],     qhf, b0);
                mma16816(sacc[2 * j + 1], qhf, b1);
            }
#pragma unroll
            for (int j = 0; j < 4; j++) {
                uint32_t b0[2] = { kbh[j][0], kbh[j][1] };
                uint32_t b1[2] = { kbh[j][2], kbh[j][3] };
                mma16816(sacc[2 * j],     qlf, b0);
                mma16816(sacc[2 * j + 1], qlf, b1);
            }
        }

        float mAn = sacc[0][0], mBn = sacc[0][2];
#pragma unroll
        for (int n = 0; n < 8; n++) {
            mAn = fmaxf(mAn, fmaxf(sacc[n][0], sacc[n][1]));
            mBn = fmaxf(mBn, fmaxf(sacc[n][2], sacc[n][3]));
        }
        mAn = fmaxf(mAn, __shfl_xor_sync(0xffffffffu, mAn, 1));
        mAn = fmaxf(mAn, __shfl_xor_sync(0xffffffffu, mAn, 2));
        mBn = fmaxf(mBn, __shfl_xor_sync(0xffffffffu, mBn, 1));
        mBn = fmaxf(mBn, __shfl_xor_sync(0xffffffffu, mBn, 2));

        // warp-uniform rescale skip: if no row's max grew, corrections are exactly 1.0
        const bool grew = (mAn > mA) || (mBn > mB);
        if (__any_sync(0xffffffffu, grew)) {
            float mA2 = fmaxf(mA, mAn), mB2 = fmaxf(mB, mBn);
            float cA = exp2f((mA - mA2) * CSC), cB = exp2f((mB - mB2) * CSC);
            mA = mA2; mB = mB2;
            lA *= cA; lB *= cB;
#pragma unroll
            for (int n = 0; n < 8; n++) {
                oacc[n][0] *= cA; oacc[n][1] *= cA;
                oacc[n][2] *= cB; oacc[n][3] *= cB;
            }
        }
#pragma unroll
        for (int n = 0; n < 8; n++) {
            sacc[n][0] = exp2f((sacc[n][0] - mA) * CSC);
            sacc[n][1] = exp2f((sacc[n][1] - mA) * CSC);
            sacc[n][2] = exp2f((sacc[n][2] - mB) * CSC);
            sacc[n][3] = exp2f((sacc[n][3] - mB) * CSC);
            lA += sacc[n][0] + sacc[n][1];
            lB += sacc[n][2] + sacc[n][3];
        }

#pragma unroll
        for (int kk = 0; kk < 4; kk++) {
            uint32_t vbh[4][4], vbl[4][4];
#pragma unroll
            for (int j = 0; j < 4; j++) {
                int key = kk * 16 + (lane & 7) + ((lane >> 3) & 1) * 8;
                uint32_t off = key * FPB + j * 32 + (lane >> 4) * 16;
                ldsm4t(vbh[j], base + FVH + off);
                ldsm4t(vbl[j], base + FVL + off);
            }
            float p00 = sacc[2 * kk][0],     p01 = sacc[2 * kk][1];
            float p10 = sacc[2 * kk][2],     p11 = sacc[2 * kk][3];
            float r00 = sacc[2 * kk + 1][0], r01 = sacc[2 * kk + 1][1];
            float r10 = sacc[2 * kk + 1][2], r11 = sacc[2 * kk + 1][3];
            uint32_t ph[4], pl[4];
            ph[0] = packbf2(p00, p01); ph[1] = packbf2(p10, p11);
            ph[2] = packbf2(r00, r01); ph[3] = packbf2(r10, r11);
            pl[0] = packbf2(p00 - hibf(p00), p01 - hibf(p01));
            pl[1] = packbf2(p10 - hibf(p10), p11 - hibf(p11));
            pl[2] = packbf2(r00 - hibf(r00), r01 - hibf(r01));
            pl[3] = packbf2(r10 - hibf(r10), r11 - hibf(r11));
#pragma unroll
            for (int j = 0; j < 4; j++) {
                uint32_t b0[2] = { vbh[j][0], vbh[j][1] };
                uint32_t b1[2] = { vbh[j][2], vbh[j][3] };
                mma16816(oacc[2 * j],     ph, b0);
                mma16816(oacc[2 * j + 1], ph, b1);
            }
#pragma unroll
            for (int j = 0; j < 4; j++) {
                uint32_t b0[2] = { vbh[j][0], vbh[j][1] };
                uint32_t b1[2] = { vbh[j][2], vbh[j][3] };
                mma16816(oacc[2 * j],     pl, b0);
                mma16816(oacc[2 * j + 1], pl, b1);
            }
#pragma unroll
            for (int j = 0; j < 4; j++) {
                uint32_t b0[2] = { vbl[j][0], vbl[j][1] };
                uint32_t b1[2] = { vbl[j][2], vbl[j][3] };
                mma16816(oacc[2 * j],     ph, b0);
                mma16816(oacc[2 * j + 1], ph, b1);
            }
        }
        __syncthreads();
        if (kt + 2 < LQ / 64) { ldkv(kt + 2, kt & 1); cpcommit(); }
    }

    lA += __shfl_xor_sync(0xffffffffu, lA, 1);
    lA += __shfl_xor_sync(0xffffffffu, lA, 2);
    lB += __shfl_xor_sync(0xffffffffu, lB, 1);
    lB += __shfl_xor_sync(0xffffffffu, lB, 2);
    const float invA = 1.f / lA, invB = 1.f / lB;
    const int rowA = m0 + (lane >> 2);
    const int rowB = rowA + 8;
    const size_t tokA = (size_t)(b * SQ + 2 * (qt * 128 + rowA) + di);
    const size_t tokB = (size_t)(b * SQ + 2 * (qt * 128 + rowB) + di);
#pragma unroll
    for (int n = 0; n < 8; n++) {
        const int col = h * DH + n * 8 + (lane & 3) * 2;
        float a0 = oacc[n][0] * invA, a1 = oacc[n][1] * invA;
        float b0 = oacc[n][2] * invB, b1 = oacc[n][3] * invB;
        *(uint32_t*)(och + tokA * DM + col) = packbf2(a0, a1);
        *(uint32_t*)(ocl + tokA * DM + col) = packbf2(a0 - hibf(a0), a1 - hibf(a1));
        *(uint32_t*)(och + tokB * DM + col) = packbf2(b0, b1);
        *(uint32_t*)(ocl + tokB * DM + col) = packbf2(b0 - hibf(b0), b1 - hibf(b1));
    }
}

// ---------------- LayerNorm (optionally emits bf16 hi/lo too) -----------------
template <bool SPLITOUT>
__global__ void __launch_bounds__(256)
ln_kernel(const float* __restrict__ X, const float* __restrict__ gam,
          const float* __restrict__ bet, float* __restrict__ Y,
          __nv_bfloat16* __restrict__ H, __nv_bfloat16* __restrict__ L)
{
    __shared__ float red[16];
    const int row = blockIdx.x;
    const int tid = threadIdx.x;

    float4 v = ((const float4*)(X + (size_t)row * DM))[tid];
    float s = v.x + v.y + v.z + v.w;
    float q = v.x * v.x + v.y * v.y + v.z * v.z + v.w * v.w;

#pragma unroll
    for (int o = 16; o; o >>= 1) {
        s += __shfl_down_sync(0xffffffffu, s, o);
        q += __shfl_down_sync(0xffffffffu, q, o);
    }
    if ((tid & 31) == 0) { red[tid >> 5] = s; red[8 + (tid >> 5)] = q; }
    __syncthreads();
    if (tid < 32) {
        float ss = (tid < 8) ? red[tid] : 0.f;
        float qq = (tid < 8) ? red[8 + tid] : 0.f;
#pragma unroll
        for (int o = 4; o; o >>= 1) {
            ss += __shfl_down_sync(0xffffffffu, ss, o);
            qq += __shfl_down_sync(0xffffffffu, qq, o);
        }
        if (tid == 0) { red[0] = ss; red[1] = qq; }
    }
    __syncthreads();

    const float mu   = red[0] * (1.f / DM);
    const float var  = red[1] * (1.f / DM) - mu * mu;
    const float rstd = rsqrtf(var + 1e-5f);

    float4 gv = ((const float4*)gam)[tid];
    float4 bv = ((const float4*)bet)[tid];
    float4 o;
    o.x = (v.x - mu) * rstd * gv.x + bv.x;
    o.y = (v.y - mu) * rstd * gv.y + bv.y;
    o.z = (v.z - mu) * rstd * gv.z + bv.z;
    o.w = (v.w - mu) * rstd * gv.w + bv.w;
    ((float4*)(Y + (size_t)row * DM))[tid] = o;
    if (SPLITOUT) {
        size_t i = (size_t)row * (DM / 4) + tid;
        ((uint32_t*)H)[i * 2 + 0] = packbf2(o.x, o.y);
        ((uint32_t*)H)[i * 2 + 1] = packbf2(o.z, o.w);
        ((uint32_t*)L)[i * 2 + 0] = packbf2(o.x - hibf(o.x), o.y - hibf(o.y));
        ((uint32_t*)L)[i * 2 + 1] = packbf2(o.z - hibf(o.z), o.w - hibf(o.w));
    }
}

// ---------------- launch ------------------------------------------------------
extern "C" void kernel_launch(void* const* d_in, const int* in_sizes, int n_in,
                              void* d_out, int out_size)
{
    const float* x     = (const float*)d_in[0];
    const float* Wq    = (const float*)d_in[1];
    const float* bq    = (const float*)d_in[2];
    const float* Wk    = (const float*)d_in[3];
    const float* bk    = (const float*)d_in[4];
    const float* Wv    = (const float*)d_in[5];
    const float* bv    = (const float*)d_in[6];
    const float* Wo    = (const float*)d_in[7];
    const float* bo    = (const float*)d_in[8];
    const float* ln1_g = (const float*)d_in[9];
    const float* ln1_b = (const float*)d_in[10];
    const float* W1    = (const float*)d_in[11];
    const float* b1    = (const float*)d_in[12];
    const float* W2    = (const float*)d_in[13];
    const float* b2    = (const float*)d_in[14];
    const float* ln2_g = (const float*)d_in[15];
    const float* ln2_b = (const float*)d_in[16];
    float* out = (float*)d_out;

    float *res1, *fin, *res2, *bqkv;
    cudaGetSymbolAddress((void**)&res1, g_res1);
    cudaGetSymbolAddress((void**)&fin,  g_fin);
    cudaGetSymbolAddress((void**)&res2, g_res2);
    cudaGetSymbolAddress((void**)&bqkv, g_bqkv);

    __nv_bfloat16 *xh, *xl, *qkvh, *qkvl, *ch, *cl, *fh, *fl, *hh, *hl;
    __nv_bfloat16 *wqkvh, *wqkvl, *woh, *wol, *w1h, *w1l, *w2h, *w2l;
    cudaGetSymbolAddress((void**)&xh,    g_xh);    cudaGetSymbolAddress((void**)&xl,    g_xl);
    cudaGetSymbolAddress((void**)&qkvh,  g_qkvh);  cudaGetSymbolAddress((void**)&qkvl,  g_qkvl);
    cudaGetSymbolAddress((void**)&ch,    g_ch);    cudaGetSymbolAddress((void**)&cl,    g_cl);
    cudaGetSymbolAddress((void**)&fh,    g_fh);    cudaGetSymbolAddress((void**)&fl,    g_fl);
    cudaGetSymbolAddress((void**)&hh,    g_hh);    cudaGetSymbolAddress((void**)&hl,    g_hl);
    cudaGetSymbolAddress((void**)&wqkvh, g_wqkvh); cudaGetSymbolAddress((void**)&wqkvl, g_wqkvl);
    cudaGetSymbolAddress((void**)&woh,   g_woh);   cudaGetSymbolAddress((void**)&wol,   g_wol);
    cudaGetSymbolAddress((void**)&w1h,   g_w1h);   cudaGetSymbolAddress((void**)&w1l,   g_w1l);
    cudaGetSymbolAddress((void**)&w2h,   g_w2h);   cudaGetSymbolAddress((void**)&w2l,   g_w2l);

    cudaFuncSetAttribute(tgemm_kernel<0, true >, cudaFuncAttributeMaxDynamicSharedMemorySize, DYN_SMEM);
    cudaFuncSetAttribute(tgemm_kernel<1, false>, cudaFuncAttributeMaxDynamicSharedMemorySize, DYN_SMEM);
    cudaFuncSetAttribute(tgemm_kernel<2, true >, cudaFuncAttributeMaxDynamicSharedMemorySize, DYN_SMEM);
    cudaFuncSetAttribute(flashmma_kernel, cudaFuncAttributeMaxDynamicSharedMemorySize, FLASH_SMEM);

    const int NB = 256;
    split_kernel<<<(MTOK * DM / 4 + NB - 1) / NB, NB>>>(x, xh, xl, MTOK * DM / 4);
    splitw_kernel<<<(4 * DD4 + 2 * DH4 + QKS + NB - 1) / NB, NB>>>(
        Wq, Wk, Wv, Wo, W1, W2, bq, bk, bv, bqkv,
        wqkvh, wqkvl, woh, wol, w1h, w1l, w2h, w2l);

    dim3 gQKV(QKS / 128, MTOK / 128);  // (24, 64)
    dim3 gD(DM / 128, MTOK / 128);     // (8, 64)
    dim3 gH(HID / 128, MTOK / 128);    // (32, 64)

    // fused QKV projection -> strided bf16 hi/lo
    tgemm_kernel<0, true><<<gQKV, 256, DYN_SMEM>>>(xh, xl, wqkvh, wqkvl, bqkv, nullptr,
                                                   nullptr, qkvh, qkvl, MTOK, QKS, DM);

    // HMMA flash attention -> ctx bf16 hi/lo
    flashmma_kernel<<<dim3(BQ * DIL * NH, LQ / 128), 256, FLASH_SMEM>>>(qkvh, qkvl, ch, cl);

    // output projection + residual + LN1 (LN emits fin fp32 + fh/fl bf16)
    tgemm_kernel<1, false><<<gD, 256, DYN_SMEM>>>(ch, cl, woh, wol, bo, x, res1, nullptr, nullptr, MTOK, DM, DM);
    ln_kernel<true><<<MTOK, 256>>>(res1, ln1_g, ln1_b, fin, fh, fl);

    // FFN
    tgemm_kernel<2, true><<<gH, 256, DYN_SMEM>>>(fh, fl, w1h, w1l, b1, nullptr, nullptr, hh, hl, MTOK, HID, DM);
    tgemm_kernel<1, false><<<gD, 256, DYN_SMEM>>>(hh, hl, w2h, w2l, b2, fin, res2, nullptr, nullptr, MTOK, DM, HID);
    ln_kernel<false><<<MTOK, 256>>>(res2, ln2_g, ln2_b, out, nullptr, nullptr);
}

// round 17
// speedup vs baseline: 1.0702x; 1.0702x over previous
#include <cuda_runtime.h>
#include <cuda_bf16.h>
#include <cstdint>

// Problem dims (fixed by reference)
#define BQ    4
#define SQ    2048
#define DM    1024
#define HID   4096
#define NH    16
#define DH    64
#define DIL   2
#define LQ    (SQ / DIL)          // 1024
#define MTOK  (BQ * SQ)           // 8192 tokens
#define QKS   3072                // concatenated QKV width

// ---------------- scratch (static device globals) ---------------------------
__device__ float g_pp  [2 * (size_t)MTOK * DM];   // split-K partial planes
__device__ float g_fin [(size_t)MTOK * DM];
__device__ float g_bqkv[QKS];

// bf16 hi/lo buffers
__device__ __nv_bfloat16 g_xh[(size_t)MTOK * DM];
__device__ __nv_bfloat16 g_xl[(size_t)MTOK * DM];
__device__ __nv_bfloat16 g_qkvh[(size_t)MTOK * QKS];
__device__ __nv_bfloat16 g_qkvl[(size_t)MTOK * QKS];
__device__ __nv_bfloat16 g_ch[(size_t)MTOK * DM];
__device__ __nv_bfloat16 g_cl[(size_t)MTOK * DM];
__device__ __nv_bfloat16 g_fh[(size_t)MTOK * DM];
__device__ __nv_bfloat16 g_fl[(size_t)MTOK * DM];
__device__ __nv_bfloat16 g_hh[(size_t)MTOK * HID];
__device__ __nv_bfloat16 g_hl[(size_t)MTOK * HID];
__device__ __nv_bfloat16 g_wqkvh[(size_t)DM * QKS];
__device__ __nv_bfloat16 g_wqkvl[(size_t)DM * QKS];
__device__ __nv_bfloat16 g_woh[(size_t)DM * DM];
__device__ __nv_bfloat16 g_wol[(size_t)DM * DM];
__device__ __nv_bfloat16 g_w1h[(size_t)DM * HID];
__device__ __nv_bfloat16 g_w1l[(size_t)DM * HID];
__device__ __nv_bfloat16 g_w2h[(size_t)HID * DM];
__device__ __nv_bfloat16 g_w2l[(size_t)HID * DM];

// ---------------- helpers ----------------------------------------------------
__device__ __forceinline__ uint32_t s2u(const void* p) {
    uint32_t a;
    asm("{ .reg .u64 t; cvta.to.shared.u64 t, %1; cvt.u32.u64 %0, t; }" : "=r"(a) : "l"(p));
    return a;
}

__device__ __forceinline__ uint32_t packbf2(float a, float b) {
    __nv_bfloat162 t;
    t.x = __float2bfloat16(a);
    t.y = __float2bfloat16(b);
    return *(uint32_t*)&t;
}

__device__ __forceinline__ float hibf(float a) {
    return __bfloat162float(__float2bfloat16(a));
}

__device__ __forceinline__ void mma16816(float* d, const uint32_t* a, const uint32_t* b) {
    asm volatile(
        "mma.sync.aligned.m16n8k16.row.col.f32.bf16.bf16.f32 "
        "{%0,%1,%2,%3}, {%4,%5,%6,%7}, {%8,%9}, {%0,%1,%2,%3};"
        : "+f"(d[0]), "+f"(d[1]), "+f"(d[2]), "+f"(d[3])
        : "r"(a[0]), "r"(a[1]), "r"(a[2]), "r"(a[3]), "r"(b[0]), "r"(b[1]));
}

__device__ __forceinline__ void ldsm4(uint32_t* r, uint32_t addr) {
    asm volatile("ldmatrix.sync.aligned.m8n8.x4.shared.b16 {%0,%1,%2,%3}, [%4];"
                 : "=r"(r[0]), "=r"(r[1]), "=r"(r[2]), "=r"(r[3]) : "r"(addr));
}

__device__ __forceinline__ void ldsm4t(uint32_t* r, uint32_t addr) {
    asm volatile("ldmatrix.sync.aligned.m8n8.x4.trans.shared.b16 {%0,%1,%2,%3}, [%4];"
                 : "=r"(r[0]), "=r"(r[1]), "=r"(r[2]), "=r"(r[3]) : "r"(addr));
}

__device__ __forceinline__ void cpasync16(uint32_t dst, const void* src) {
    asm volatile("cp.async.cg.shared.global [%0], [%1], 16;" :: "r"(dst), "l"(src));
}
__device__ __forceinline__ void cpcommit() {
    asm volatile("cp.async.commit_group;" ::: "memory");
}
__device__ __forceinline__ void cpwait1() {
    asm volatile("cp.async.wait_group 1;" ::: "memory");
}
__device__ __forceinline__ void cpwait0() {
    asm volatile("cp.async.wait_group 0;" ::: "memory");
}

// ---------------- bf16x3 HMMA GEMM: 3-stage, single barrier per chunk --------
// MODE 0: +bias   MODE 2: relu(+bias)   MODE 3: raw fp32 partial (split-K via z)
#define KT   32
#define PA   40
#define PB   136
#define ASZ  (128 * PA * 2)
#define BSZ  (KT * PB * 2)
#define STG  (2 * ASZ + 2 * BSZ)    // 37888 B per stage
#define DYN_SMEM (3 * STG)          // 113664 B; 2 CTAs/SM

template <int MODE, bool OUTBF16>
__global__ void __launch_bounds__(256, 2)
tgemm_kernel(const __nv_bfloat16* __restrict__ Ah, const __nv_bfloat16* __restrict__ Al,
             const __nv_bfloat16* __restrict__ Wh, const __nv_bfloat16* __restrict__ Wl,
             const float* __restrict__ bias,
             float* __restrict__ C, __nv_bfloat16* __restrict__ Ch,
             __nv_bfloat16* __restrict__ Cl, int M, int N, int Kd, int Klen)
{
    extern __shared__ __align__(16) char smem[];
    const uint32_t sb = s2u(smem);
    const int tid  = threadIdx.x;
    const int lane = tid & 31;
    const int wid  = tid >> 5;
    const int bm   = blockIdx.y;
    const int bn   = blockIdx.x;
    const int wm0  = (wid & 1) * 64;
    const int wn0  = (wid >> 1) * 32;

    // split-K offset (z) — Kd is the A row stride, Klen this part's length
    const int koff = blockIdx.z * Klen;
    Ah += koff; Al += koff;
    Wh += (size_t)koff * N; Wl += (size_t)koff * N;
    if (MODE == 3) C += (size_t)blockIdx.z * M * N;

    const int ar  = tid >> 1;
    const int ak0 = (tid & 1) * 16;
    const int bk  = tid >> 3;
    const int bn0 = (tid & 7) * 16;

    const size_t aoff = (size_t)(bm * 128 + ar) * Kd + ak0;
    const size_t boff = (size_t)bk * N + bn * 128 + bn0;

    float acc[4][4][4];
#pragma unroll
    for (int i = 0; i < 4; i++)
#pragma unroll
        for (int j = 0; j < 4; j++)
#pragma unroll
            for (int l = 0; l < 4; l++) acc[i][j][l] = 0.f;

    const int nk = Klen / KT;

    auto issue_loads = [&](int kb, int buf) {
        const uint32_t s = sb + buf * STG;
        const uint32_t dAh = s + (ar * PA + ak0) * 2;
        const uint32_t dAl = dAh + ASZ;
        const uint32_t dBh = s + 2 * ASZ + (bk * PB + bn0) * 2;
        const uint32_t dBl = dBh + BSZ;
        const __nv_bfloat16* pAh = Ah + aoff + (size_t)kb * KT;
        const __nv_bfloat16* pAl = Al + aoff + (size_t)kb * KT;
        const __nv_bfloat16* pBh = Wh + boff + (size_t)kb * KT * N;
        const __nv_bfloat16* pBl = Wl + boff + (size_t)kb * KT * N;
        cpasync16(dAh,      pAh);
        cpasync16(dAh + 16, pAh + 8);
        cpasync16(dAl,      pAl);
        cpasync16(dAl + 16, pAl + 8);
        cpasync16(dBh,      pBh);
        cpasync16(dBh + 16, pBh + 8);
        cpasync16(dBl,      pBl);
        cpasync16(dBl + 16, pBl + 8);
        cpcommit();
    };

    auto compute_k16 = [&](int buf, int ks) {
        const uint32_t base = sb + buf * STG;
        const uint32_t aAh = base;
        const uint32_t aAl = base + ASZ;
        const uint32_t aBh = base + 2 * ASZ;
        const uint32_t aBl = base + 2 * ASZ + BSZ;
        const int lr = lane & 15;
        const int lc = (lane >> 4) * 8;
        uint32_t bh[2][4], bl[2][4];
#pragma unroll
        for (int g = 0; g < 2; g++) {
            uint32_t off = ((ks + lr) * PB + wn0 + g * 16 + lc) * 2;
            ldsm4t(bh[g], aBh + off);
            ldsm4t(bl[g], aBl + off);
        }
#pragma unroll
        for (int mp = 0; mp < 4; mp += 2) {
            uint32_t ah[2][4], al[2][4];
#pragma unroll
            for (int i = 0; i < 2; i++) {
                uint32_t off = ((wm0 + (mp + i) * 16 + lr) * PA + ks + lc) * 2;
                ldsm4(ah[i], aAh + off);
                ldsm4(al[i], aAl + off);
            }
#pragma unroll
            for (int i = 0; i < 2; i++)
#pragma unroll
                for (int nt = 0; nt < 4; nt++) {
                    const int g = nt >> 1, q = (nt & 1) * 2;
                    uint32_t bb[2] = { bh[g][q], bh[g][q + 1] };
                    mma16816(acc[mp + i][nt], ah[i], bb);
                }
#pragma unroll
            for (int i = 0; i < 2; i++)
#pragma unroll
                for (int nt = 0; nt < 4; nt++) {
                    const int g = nt >> 1, q = (nt & 1) * 2;
                    uint32_t bb[2] = { bl[g][q], bl[g][q + 1] };
                    mma16816(acc[mp + i][nt], ah[i], bb);
                }
#pragma unroll
            for (int i = 0; i < 2; i++)
#pragma unroll
                for (int nt = 0; nt < 4; nt++) {
                    const int g = nt >> 1, q = (nt & 1) * 2;
                    uint32_t bb[2] = { bh[g][q], bh[g][q + 1] };
                    mma16816(acc[mp + i][nt], al[i], bb);
                }
        }
    };

    // prologue: 2 chunks in flight
    issue_loads(0, 0);
    issue_loads(1, 1);
    for (int kb = 0; kb < nk; kb++) {
        if (kb < nk - 1) cpwait1(); else cpwait0();
        __syncthreads();
        const int buf = kb % 3;
        compute_k16(buf, 0);
        if (kb + 2 < nk) issue_loads(kb + 2, (kb + 2) % 3);
        compute_k16(buf, 16);
    }

    const int rbase = bm * 128 + wm0 + (lane >> 2);
    const int cbase = bn * 128 + wn0 + (lane & 3) * 2;
#pragma unroll
    for (int mt = 0; mt < 4; mt++) {
#pragma unroll
        for (int hf = 0; hf < 2; hf++) {
            const int row = rbase + mt * 16 + hf * 8;
#pragma unroll
            for (int nt = 0; nt < 4; nt++) {
                const int col = cbase + nt * 8;
                float v0 = acc[mt][nt][hf * 2 + 0];
                float v1 = acc[mt][nt][hf * 2 + 1];
                if (MODE != 3) { v0 += bias[col]; v1 += bias[col + 1]; }
                if (MODE == 2) { v0 = fmaxf(v0, 0.f); v1 = fmaxf(v1, 0.f); }
                if (OUTBF16) {
                    *(uint32_t*)(Ch + (size_t)row * N + col) = packbf2(v0, v1);
                    *(uint32_t*)(Cl + (size_t)row * N + col) =
                        packbf2(v0 - hibf(v0), v1 - hibf(v1));
                } else {
                    float2 o; o.x = v0; o.y = v1;
                    *(float2*)(C + (size_t)row * N + col) = o;
                }
            }
        }
    }
}

// ---------------- splits ------------------------------------------------------
__device__ __forceinline__ void split_one2(const float* __restrict__ X, int si,
                                           __nv_bfloat16* __restrict__ H,
                                           __nv_bfloat16* __restrict__ L, int di)
{
    float4 v = ((const float4*)X)[si];
    ((uint32_t*)H)[di * 2 + 0] = packbf2(v.x, v.y);
    ((uint32_t*)H)[di * 2 + 1] = packbf2(v.z, v.w);
    ((uint32_t*)L)[di * 2 + 0] = packbf2(v.x - hibf(v.x), v.y - hibf(v.y));
    ((uint32_t*)L)[di * 2 + 1] = packbf2(v.z - hibf(v.z), v.w - hibf(v.w));
}

__global__ void __launch_bounds__(256)
split_kernel(const float* __restrict__ X, __nv_bfloat16* __restrict__ H,
             __nv_bfloat16* __restrict__ L, int n4)
{
    int i = blockIdx.x * blockDim.x + threadIdx.x;
    if (i < n4) split_one2(X, i, H, L, i);
}

#define DD4 (DM * DM / 4)
#define DH4 (DM * HID / 4)
__global__ void __launch_bounds__(256)
splitw_kernel(const float* Wq, const float* Wk, const float* Wv, const float* Wo,
              const float* W1, const float* W2,
              const float* bq, const float* bk, const float* bv, float* bqkv,
              __nv_bfloat16* wqkvh, __nv_bfloat16* wqkvl,
              __nv_bfloat16* woh, __nv_bfloat16* wol,
              __nv_bfloat16* w1h, __nv_bfloat16* w1l,
              __nv_bfloat16* w2h, __nv_bfloat16* w2l)
{
    int i = blockIdx.x * blockDim.x + threadIdx.x;
    if (i < 3 * DD4) {
        int m = i / DD4;                  // 0=q 1=k 2=v
        int j = i - m * DD4;
        int k = j >> 8;
        int c = j & 255;
        const float* src = (m == 0) ? Wq : (m == 1) ? Wk : Wv;
        split_one2(src, j, wqkvh, wqkvl, k * (QKS / 4) + m * 256 + c);
    } else {
        int j = i - 3 * DD4;
        if (j < DD4)                 split_one2(Wo, j, woh, wol, j);
        else if (j < DD4 + DH4)      split_one2(W1, j - DD4, w1h, w1l, j - DD4);
        else if (j < DD4 + 2 * DH4)  split_one2(W2, j - DD4 - DH4, w2h, w2l, j - DD4 - DH4);
        else {
            int t = j - DD4 - 2 * DH4;   // 0..QKS-1
            if (t < DM)            bqkv[t] = bq[t];
            else if (t < 2 * DM)   bqkv[t] = bk[t - DM];
            else if (t < 3 * DM)   bqkv[t] = bv[t - 2 * DM];
        }
    }
}

// ---------------- HMMA flash attention (reads strided QKV buffer) ------------
#define FP    72
#define FPB   144
#define FQH   0
#define FQL   18432
#define FKV0  36864
#define FSSZ  36864
#define FKH   0
#define FKL   9216
#define FVH   18432
#define FVL   27648
#define FLASH_SMEM (36864 + 2 * FSSZ)
#define CSC   0.180336879f

__global__ void __launch_bounds__(256, 2)
flashmma_kernel(const __nv_bfloat16* __restrict__ qkvh, const __nv_bfloat16* __restrict__ qkvl,
                __nv_bfloat16* __restrict__ och, __nv_bfloat16* __restrict__ ocl)
{
    extern __shared__ __align__(16) char fsm[];
    const uint32_t sb = s2u(fsm);
    const int tid  = threadIdx.x;
    const int lane = tid & 31;
    const int w    = tid >> 5;
    const int gh   = blockIdx.x;
    const int qt   = blockIdx.y;
    const int g    = gh >> 4;
    const int h    = gh & 15;
    const int b    = g >> 1;
    const int di   = g & 1;
    const int m0   = w * 16;

    const __nv_bfloat16* qh = qkvh;
    const __nv_bfloat16* ql = qkvl;
    const __nv_bfloat16* kh = qkvh + DM;
    const __nv_bfloat16* kl = qkvl + DM;
    const __nv_bfloat16* vh = qkvh + 2 * DM;
    const __nv_bfloat16* vl = qkvl + 2 * DM;

    auto ldq = [&]() {
#pragma unroll
        for (int i = 0; i < 8; i++) {
            int c   = tid + i * 256;
            int hf  = c >> 10;
            int cc  = c & 1023;
            int row = cc >> 3;
            int o   = cc & 7;
            size_t tok = (size_t)(b * SQ + 2 * (qt * 128 + row) + di);
            const __nv_bfloat16* src = (hf ? ql : qh) + tok * QKS + h * DH + o * 8;
            cpasync16(sb + (hf ? FQL : FQH) + row * FPB + o * 16, src);
        }
    };
    auto ldkv = [&](int kt, int s) {
        const uint32_t base = sb + FKV0 + s * FSSZ;
#pragma unroll
        for (int i = 0; i < 8; i++) {
            int c   = tid + i * 256;
            int mat = c >> 9;
            int cc  = c & 511;
            int row = cc >> 3;
            int o   = cc & 7;
            size_t tok = (size_t)(b * SQ + 2 * (kt * 64 + row) + di);
            const __nv_bfloat16* srcp =
                (mat == 0) ? kh : (mat == 1) ? kl : (mat == 2) ? vh : vl;
            cpasync16(base + mat * 9216 + row * FPB + o * 16, srcp + tok * QKS + h * DH + o * 8);
        }
    };

    ldq();
    ldkv(0, 0);
    cpcommit();
    ldkv(1, 1);
    cpcommit();

    float oacc[8][4];
#pragma unroll
    for (int n = 0; n < 8; n++)
#pragma unroll
        for (int i = 0; i < 4; i++) oacc[n][i] = 0.f;
    float mA = -1e30f, mB = -1e30f, lA = 0.f, lB = 0.f;

    const int arow = (lane & 7) + ((lane >> 3) & 1) * 8;
    const int acol = (lane >> 4) * 16;

    for (int kt = 0; kt < LQ / 64; kt++) {
        if (kt == LQ / 64 - 1) cpwait0(); else cpwait1();
        __syncthreads();
        const uint32_t base = sb + FKV0 + (kt & 1) * FSSZ;

        float sacc[8][4];
#pragma unroll
        for (int n = 0; n < 8; n++)
#pragma unroll
            for (int i = 0; i < 4; i++) sacc[n][i] = 0.f;

#pragma unroll
        for (int kk = 0; kk < 4; kk++) {
            uint32_t qhf[4], qlf[4];
            {
                uint32_t qoff = (m0 + arow) * FPB + kk * 32 + acol;
                ldsm4(qhf, sb + FQH + qoff);
                ldsm4(qlf, sb + FQL + qoff);
            }
            uint32_t kbh[4][4], kbl[4][4];
#pragma unroll
            for (int j = 0; j < 4; j++) {
                int key = j * 16 + (lane & 7) + ((lane >> 4) << 3);
                uint32_t off = key * FPB + kk * 32 + ((lane >> 3) & 1) * 16;
                ldsm4(kbh[j], base + FKH + off);
                ldsm4(kbl[j], base + FKL + off);
            }
#pragma unroll
            for (int j = 0; j < 4; j++) {
                uint32_t b0[2] = { kbh[j][0], kbh[j][1] };
                uint32_t b1[2] = { kbh[j][2], kbh[j][3] };
                mma16816(sacc[2 * j],     qhf, b0);
                mma16816(sacc[2 * j + 1], qhf, b1);
            }
#pragma unroll
            for (int j = 0; j < 4; j++) {
                uint32_t b0[2] = { kbl[j][0], kbl[j][1] };
                uint32_t b1[2] = { kbl[j][2], kbl[j][3] };
                mma16816(sacc[2 * j],     qhf, b0);
                mma16816(sacc[2 * j + 1], qhf, b1);
            }
#pragma unroll
            for (int j = 0; j < 4; j++) {
                uint32_t b0[2] = { kbh[j][0], kbh[j][1] };
                uint32_t b1[2] = { kbh[j][2], kbh[j][3] };
                mma16816(sacc[2 * j],     qlf, b0);
                mma16816(sacc[2 * j + 1], qlf, b1);
            }
        }

        float mAn = sacc[0][0], mBn = sacc[0][2];
#pragma unroll
        for (int n = 0; n < 8; n++) {
            mAn = fmaxf(mAn, fmaxf(sacc[n][0], sacc[n][1]));
            mBn = fmaxf(mBn, fmaxf(sacc[n][2], sacc[n][3]));
        }
        mAn = fmaxf(mAn, __shfl_xor_sync(0xffffffffu, mAn, 1));
        mAn = fmaxf(mAn, __shfl_xor_sync(0xffffffffu, mAn, 2));
        mBn = fmaxf(mBn, __shfl_xor_sync(0xffffffffu, mBn, 1));
        mBn = fmaxf(mBn, __shfl_xor_sync(0xffffffffu, mBn, 2));

        const bool grew = (mAn > mA) || (mBn > mB);
        if (__any_sync(0xffffffffu, grew)) {
            float mA2 = fmaxf(mA, mAn), mB2 = fmaxf(mB, mBn);
            float cA = exp2f((mA - mA2) * CSC), cB = exp2f((mB - mB2) * CSC);
            mA = mA2; mB = mB2;
            lA *= cA; lB *= cB;
#pragma unroll
            for (int n = 0; n < 8; n++) {
                oacc[n][0] *= cA; oacc[n][1] *= cA;
                oacc[n][2] *= cB; oacc[n][3] *= cB;
            }
        }
#pragma unroll
        for (int n = 0; n < 8; n++) {
            sacc[n][0] = exp2f((sacc[n][0] - mA) * CSC);
            sacc[n][1] = exp2f((sacc[n][1] - mA) * CSC);
            sacc[n][2] = exp2f((sacc[n][2] - mB) * CSC);
            sacc[n][3] = exp2f((sacc[n][3] - mB) * CSC);
            lA += sacc[n][0] + sacc[n][1];
            lB += sacc[n][2] + sacc[n][3];
        }

#pragma unroll
        for (int kk = 0; kk < 4; kk++) {
            uint32_t vbh[4][4], vbl[4][4];
#pragma unroll
            for (int j = 0; j < 4; j++) {
                int key = kk * 16 + (lane & 7) + ((lane >> 3) & 1) * 8;
                uint32_t off = key * FPB + j * 32 + (lane >> 4) * 16;
                ldsm4t(vbh[j], base + FVH + off);
                ldsm4t(vbl[j], base + FVL + off);
            }
            float p00 = sacc[2 * kk][0],     p01 = sacc[2 * kk][1];
            float p10 = sacc[2 * kk][2],     p11 = sacc[2 * kk][3];
            float r00 = sacc[2 * kk + 1][0], r01 = sacc[2 * kk + 1][1];
            float r10 = sacc[2 * kk + 1][2], r11 = sacc[2 * kk + 1][3];
            uint32_t ph[4], pl[4];
            ph[0] = packbf2(p00, p01); ph[1] = packbf2(p10, p11);
            ph[2] = packbf2(r00, r01); ph[3] = packbf2(r10, r11);
            pl[0] = packbf2(p00 - hibf(p00), p01 - hibf(p01));
            pl[1] = packbf2(p10 - hibf(p10), p11 - hibf(p11));
            pl[2] = packbf2(r00 - hibf(r00), r01 - hibf(r01));
            pl[3] = packbf2(r10 - hibf(r10), r11 - hibf(r11));
#pragma unroll
            for (int j = 0; j < 4; j++) {
                uint32_t b0[2] = { vbh[j][0], vbh[j][1] };
                uint32_t b1[2] = { vbh[j][2], vbh[j][3] };
                mma16816(oacc[2 * j],     ph, b0);
                mma16816(oacc[2 * j + 1], ph, b1);
            }
#pragma unroll
            for (int j = 0; j < 4; j++) {
                uint32_t b0[2] = { vbh[j][0], vbh[j][1] };
                uint32_t b1[2] = { vbh[j][2], vbh[j][3] };
                mma16816(oacc[2 * j],     pl, b0);
                mma16816(oacc[2 * j + 1], pl, b1);
            }
#pragma unroll
            for (int j = 0; j < 4; j++) {
                uint32_t b0[2] = { vbl[j][0], vbl[j][1] };
                uint32_t b1[2] = { vbl[j][2], vbl[j][3] };
                mma16816(oacc[2 * j],     ph, b0);
                mma16816(oacc[2 * j + 1], ph, b1);
            }
        }
        __syncthreads();
        if (kt + 2 < LQ / 64) { ldkv(kt + 2, kt & 1); cpcommit(); }
    }

    lA += __shfl_xor_sync(0xffffffffu, lA, 1);
    lA += __shfl_xor_sync(0xffffffffu, lA, 2);
    lB += __shfl_xor_sync(0xffffffffu, lB, 1);
    lB += __shfl_xor_sync(0xffffffffu, lB, 2);
    const float invA = 1.f / lA, invB = 1.f / lB;
    const int rowA = m0 + (lane >> 2);
    const int rowB = rowA + 8;
    const size_t tokA = (size_t)(b * SQ + 2 * (qt * 128 + rowA) + di);
    const size_t tokB = (size_t)(b * SQ + 2 * (qt * 128 + rowB) + di);
#pragma unroll
    for (int n = 0; n < 8; n++) {
        const int col = h * DH + n * 8 + (lane & 3) * 2;
        float a0 = oacc[n][0] * invA, a1 = oacc[n][1] * invA;
        float b0 = oacc[n][2] * invB, b1 = oacc[n][3] * invB;
        *(uint32_t*)(och + tokA * DM + col) = packbf2(a0, a1);
        *(uint32_t*)(ocl + tokA * DM + col) = packbf2(a0 - hibf(a0), a1 - hibf(a1));
        *(uint32_t*)(och + tokB * DM + col) = packbf2(b0, b1);
        *(uint32_t*)(ocl + tokB * DM + col) = packbf2(b0 - hibf(b0), b1 - hibf(b1));
    }
}

// ---------------- LayerNorm over (P0 + P1 + bias + residual) ------------------
template <bool SPLITOUT>
__global__ void __launch_bounds__(256)
lncomb_kernel(const float* __restrict__ P0, const float* __restrict__ P1,
              const float* __restrict__ bias, const float* __restrict__ R,
              const float* __restrict__ gam, const float* __restrict__ bet,
              float* __restrict__ Y, __nv_bfloat16* __restrict__ H,
              __nv_bfloat16* __restrict__ L)
{
    __shared__ float red[16];
    const int row = blockIdx.x;
    const int tid = threadIdx.x;
    const size_t ro = (size_t)row * (DM / 4) + tid;

    float4 p0 = ((const float4*)P0)[ro];
    float4 p1 = ((const float4*)P1)[ro];
    float4 rr = ((const float4*)R)[ro];
    float4 bb = ((const float4*)bias)[tid];
    float4 v;
    v.x = p0.x + p1.x + rr.x + bb.x;
    v.y = p0.y + p1.y + rr.y + bb.y;
    v.z = p0.z + p1.z + rr.z + bb.z;
    v.w = p0.w + p1.w + rr.w + bb.w;

    float s = v.x + v.y + v.z + v.w;
    float q = v.x * v.x + v.y * v.y + v.z * v.z + v.w * v.w;

#pragma unroll
    for (int o = 16; o; o >>= 1) {
        s += __shfl_down_sync(0xffffffffu, s, o);
        q += __shfl_down_sync(0xffffffffu, q, o);
    }
    if ((tid & 31) == 0) { red[tid >> 5] = s; red[8 + (tid >> 5)] = q; }
    __syncthreads();
    if (tid < 32) {
        float ss = (tid < 8) ? red[tid] : 0.f;
        float qq = (tid < 8) ? red[8 + tid] : 0.f;
#pragma unroll
        for (int o = 4; o; o >>= 1) {
            ss += __shfl_down_sync(0xffffffffu, ss, o);
            qq += __shfl_down_sync(0xffffffffu, qq, o);
        }
        if (tid == 0) { red[0] = ss; red[1] = qq; }
    }
    __syncthreads();

    const float mu   = red[0] * (1.f / DM);
    const float var  = red[1] * (1.f / DM) - mu * mu;
    const float rstd = rsqrtf(var + 1e-5f);

    float4 gv = ((const float4*)gam)[tid];
    float4 bv = ((const float4*)bet)[tid];
    float4 o;
    o.x = (v.x - mu) * rstd * gv.x + bv.x;
    o.y = (v.y - mu) * rstd * gv.y + bv.y;
    o.z = (v.z - mu) * rstd * gv.z + bv.z;
    o.w = (v.w - mu) * rstd * gv.w + bv.w;
    ((float4*)Y)[ro] = o;
    if (SPLITOUT) {
        ((uint32_t*)H)[ro * 2 + 0] = packbf2(o.x, o.y);
        ((uint32_t*)H)[ro * 2 + 1] = packbf2(o.z, o.w);
        ((uint32_t*)L)[ro * 2 + 0] = packbf2(o.x - hibf(o.x), o.y - hibf(o.y));
        ((uint32_t*)L)[ro * 2 + 1] = packbf2(o.z - hibf(o.z), o.w - hibf(o.w));
    }
}

// ---------------- launch ------------------------------------------------------
extern "C" void kernel_launch(void* const* d_in, const int* in_sizes, int n_in,
                              void* d_out, int out_size)
{
    const float* x     = (const float*)d_in[0];
    const float* Wq    = (const float*)d_in[1];
    const float* bq    = (const float*)d_in[2];
    const float* Wk    = (const float*)d_in[3];
    const float* bk    = (const float*)d_in[4];
    const float* Wv    = (const float*)d_in[5];
    const float* bv    = (const float*)d_in[6];
    const float* Wo    = (const float*)d_in[7];
    const float* bo    = (const float*)d_in[8];
    const float* ln1_g = (const float*)d_in[9];
    const float* ln1_b = (const float*)d_in[10];
    const float* W1    = (const float*)d_in[11];
    const float* b1    = (const float*)d_in[12];
    const float* W2    = (const float*)d_in[13];
    const float* b2    = (const float*)d_in[14];
    const float* ln2_g = (const float*)d_in[15];
    const float* ln2_b = (const float*)d_in[16];
    float* out = (float*)d_out;

    float *pp, *fin, *bqkv;
    cudaGetSymbolAddress((void**)&pp,   g_pp);
    cudaGetSymbolAddress((void**)&fin,  g_fin);
    cudaGetSymbolAddress((void**)&bqkv, g_bqkv);
    float* pp1 = pp + (size_t)MTOK * DM;

    __nv_bfloat16 *xh, *xl, *qkvh, *qkvl, *ch, *cl, *fh, *fl, *hh, *hl;
    __nv_bfloat16 *wqkvh, *wqkvl, *woh, *wol, *w1h, *w1l, *w2h, *w2l;
    cudaGetSymbolAddress((void**)&xh,    g_xh);    cudaGetSymbolAddress((void**)&xl,    g_xl);
    cudaGetSymbolAddress((void**)&qkvh,  g_qkvh);  cudaGetSymbolAddress((void**)&qkvl,  g_qkvl);
    cudaGetSymbolAddress((void**)&ch,    g_ch);    cudaGetSymbolAddress((void**)&cl,    g_cl);
    cudaGetSymbolAddress((void**)&fh,    g_fh);    cudaGetSymbolAddress((void**)&fl,    g_fl);
    cudaGetSymbolAddress((void**)&hh,    g_hh);    cudaGetSymbolAddress((void**)&hl,    g_hl);
    cudaGetSymbolAddress((void**)&wqkvh, g_wqkvh); cudaGetSymbolAddress((void**)&wqkvl, g_wqkvl);
    cudaGetSymbolAddress((void**)&woh,   g_woh);   cudaGetSymbolAddress((void**)&wol,   g_wol);
    cudaGetSymbolAddress((void**)&w1h,   g_w1h);   cudaGetSymbolAddress((void**)&w1l,   g_w1l);
    cudaGetSymbolAddress((void**)&w2h,   g_w2h);   cudaGetSymbolAddress((void**)&w2l,   g_w2l);

    cudaFuncSetAttribute(tgemm_kernel<0, true >, cudaFuncAttributeMaxDynamicSharedMemorySize, DYN_SMEM);
    cudaFuncSetAttribute(tgemm_kernel<2, true >, cudaFuncAttributeMaxDynamicSharedMemorySize, DYN_SMEM);
    cudaFuncSetAttribute(tgemm_kernel<3, false>, cudaFuncAttributeMaxDynamicSharedMemorySize, DYN_SMEM);
    cudaFuncSetAttribute(flashmma_kernel, cudaFuncAttributeMaxDynamicSharedMemorySize, FLASH_SMEM);

    const int NB = 256;
    split_kernel<<<(MTOK * DM / 4 + NB - 1) / NB, NB>>>(x, xh, xl, MTOK * DM / 4);
    splitw_kernel<<<(4 * DD4 + 2 * DH4 + QKS + NB - 1) / NB, NB>>>(
        Wq, Wk, Wv, Wo, W1, W2, bq, bk, bv, bqkv,
        wqkvh, wqkvl, woh, wol, w1h, w1l, w2h, w2l);

    dim3 gQKV(QKS / 128, MTOK / 128, 1);   // (24, 64)
    dim3 gWo (DM / 128, MTOK / 128, 2);    // (8, 64, 2)  split-K
    dim3 gH1 (HID / 128, MTOK / 128, 1);   // (32, 64)
    dim3 gF2 (DM / 128, MTOK / 128, 2);    // (8, 64, 2)  split-K

    // fused QKV projection -> strided bf16 hi/lo
    tgemm_kernel<0, true><<<gQKV, 256, DYN_SMEM>>>(xh, xl, wqkvh, wqkvl, bqkv,
                                                   nullptr, qkvh, qkvl, MTOK, QKS, DM, DM);

    // HMMA flash attention -> ctx bf16 hi/lo
    flashmma_kernel<<<dim3(BQ * DIL * NH, LQ / 128), 256, FLASH_SMEM>>>(qkvh, qkvl, ch, cl);

    // output projection split-K=2 -> partials; LN1 combines (+bo +x) and splits
    tgemm_kernel<3, false><<<gWo, 256, DYN_SMEM>>>(ch, cl, woh, wol, nullptr,
                                                   pp, nullptr, nullptr, MTOK, DM, DM, DM / 2);
    lncomb_kernel<true><<<MTOK, 256>>>(pp, pp1, bo, x, ln1_g, ln1_b, fin, fh, fl);

    // FFN1
    tgemm_kernel<2, true><<<gH1, 256, DYN_SMEM>>>(fh, fl, w1h, w1l, b1,
                                                  nullptr, hh, hl, MTOK, HID, DM, DM);
    // FFN2 split-K=2 -> partials; LN2 combines (+b2 +fin)
    tgemm_kernel<3, false><<<gF2, 256, DYN_SMEM>>>(hh, hl, w2h, w2l, nullptr,
                                                   pp, nullptr, nullptr, MTOK, DM, HID, HID / 2);
    lncomb_kernel<false><<<MTOK, 256>>>(pp, pp1, b2, fin, ln2_g, ln2_b, out, nullptr, nullptr);
}